// round 4
// baseline (speedup 1.0000x reference)
#include <cuda_runtime.h>
#include <cuda_bf16.h>
#include <cstddef>

#define HDIM 1024
#define SLEN 4096
#define BATCH 32
#define NSB 8                              // s-blocks per batch
#define ROWS_PER_BLOCK (SLEN / NSB)        // 512
#define NWARPS 8
#define ROWS_PER_WARP (ROWS_PER_BLOCK / NWARPS)  // 64
#define NPART NSB                          // 8 block-level partials per batch
#define VCHUNKS 32                         // o-chunks for vprime

// Scratch (device globals; no allocation in kernel_launch)
__device__ float g_vpart[VCHUNKS][HDIM];           // partial U^T V
__device__ float g_vprime[HDIM];                   // reduced U^T V
__device__ float g_scores[BATCH * SLEN];           // raw scores
__device__ float g_pctx[(size_t)BATCH * NPART * HDIM]; // block partials (1 MB)
__device__ float g_pm[BATCH * NPART];
__device__ float g_pl[BATCH * NPART];
__device__ int   g_cnt[BATCH];                     // zero-init; self-resetting

// ---------------------------------------------------------------------------
// K1: v' partials. grid (8, 32), block 128.
// ---------------------------------------------------------------------------
__global__ void vprime_kernel(const float* __restrict__ U,
                              const float* __restrict__ V) {
    const int h  = blockIdx.x * 128 + threadIdx.x;
    const int oc = blockIdx.y;
    const int o0 = oc * (HDIM / VCHUNKS);
    float acc = 0.0f;
#pragma unroll 8
    for (int o = 0; o < HDIM / VCHUNKS; o++) {
        acc += U[(size_t)(o0 + o) * HDIM + h] * V[o0 + o];
    }
    g_vpart[oc][h] = acc;
}

// K1b: reduce the 32 partials. grid 8, block 128.
__global__ void vreduce_kernel() {
    const int h = blockIdx.x * 128 + threadIdx.x;
    float a = 0.0f;
#pragma unroll
    for (int oc = 0; oc < VCHUNKS; oc++) a += g_vpart[oc][h];
    g_vprime[h] = a;
}

// ---------------------------------------------------------------------------
// K2: single streaming pass over keys (512 MB, read once, __ldcs) with a
// fused epilogue: the LAST block to finish per batch (fence+atomic) merges
// the 8 block partials and writes context + softmax weights.
// grid (NSB, BATCH), block 256, occ 2.
// out layout: [context B*H | weight B*S]
// ---------------------------------------------------------------------------
__global__ void __launch_bounds__(256, 2)
main_pass_kernel(const float* __restrict__ keys, float* __restrict__ out) {
    const int b    = blockIdx.y;
    const int sb   = blockIdx.x;
    const int w    = threadIdx.x >> 5;
    const int lane = threadIdx.x & 31;
    const int t    = threadIdx.x;

    __shared__ float4 s_acc[NWARPS][256];   // 32 KB
    __shared__ float  s_m[NWARPS];
    __shared__ float  s_l[NWARPS];
    __shared__ int    s_last;

    // v' into registers: lane covers float4 index i*32+lane
    float4 vp[8];
#pragma unroll
    for (int i = 0; i < 8; i++)
        vp[i] = reinterpret_cast<const float4*>(g_vprime)[i * 32 + lane];

    float m = -3.0e38f;
    float l = 0.0f;
    float4 acc[8];
#pragma unroll
    for (int i = 0; i < 8; i++) acc[i] = make_float4(0.f, 0.f, 0.f, 0.f);

    const int s0 = sb * ROWS_PER_BLOCK + w * ROWS_PER_WARP;
    const float4* __restrict__ base =
        reinterpret_cast<const float4*>(keys + (size_t)b * SLEN * HDIM);

    for (int j = 0; j < ROWS_PER_WARP; j++) {
        const int s = s0 + j;
        const float4* __restrict__ row = base + (size_t)s * (HDIM / 4);

        float4 k[8];
#pragma unroll
        for (int i = 0; i < 8; i++) k[i] = __ldcs(row + i * 32 + lane);

        float d = 0.0f;
#pragma unroll
        for (int i = 0; i < 8; i++) {
            d += k[i].x * vp[i].x + k[i].y * vp[i].y +
                 k[i].z * vp[i].z + k[i].w * vp[i].w;
        }
#pragma unroll
        for (int off = 16; off; off >>= 1)
            d += __shfl_xor_sync(0xffffffffu, d, off);

        if (lane == 0) g_scores[b * SLEN + s] = d;

        if (d > m) {  // warp-uniform; taken ~log2(64) times
            float sc = __expf(m - d);
            l *= sc;
#pragma unroll
            for (int i = 0; i < 8; i++) {
                acc[i].x *= sc; acc[i].y *= sc; acc[i].z *= sc; acc[i].w *= sc;
            }
            m = d;
        }
        float p = __expf(d - m);
        l += p;
#pragma unroll
        for (int i = 0; i < 8; i++) {
            acc[i].x += p * k[i].x; acc[i].y += p * k[i].y;
            acc[i].z += p * k[i].z; acc[i].w += p * k[i].w;
        }
    }

    // ---- block-level merge of 8 warp partials (smem) ----
#pragma unroll
    for (int i = 0; i < 8; i++) s_acc[w][i * 32 + lane] = acc[i];
    if (lane == 0) { s_m[w] = m; s_l[w] = l; }
    __syncthreads();

    float Mb = s_m[0];
#pragma unroll
    for (int ww = 1; ww < NWARPS; ww++) Mb = fmaxf(Mb, s_m[ww]);
    float Lb = 0.0f;
    float scale[NWARPS];
#pragma unroll
    for (int ww = 0; ww < NWARPS; ww++) {
        scale[ww] = __expf(s_m[ww] - Mb);
        Lb += scale[ww] * s_l[ww];
    }

    float4 sum = make_float4(0.f, 0.f, 0.f, 0.f);
#pragma unroll
    for (int ww = 0; ww < NWARPS; ww++) {
        float4 v = s_acc[ww][t];
        const float sc = scale[ww];
        sum.x += sc * v.x; sum.y += sc * v.y;
        sum.z += sc * v.z; sum.w += sc * v.w;
    }

    const int pidx = b * NPART + sb;
    reinterpret_cast<float4*>(g_pctx + (size_t)pidx * HDIM)[t] = sum;
    if (t == 0) { g_pm[pidx] = Mb; g_pl[pidx] = Lb; }

    // ---- publish + elect last block of this batch ----
    __threadfence();
    __syncthreads();
    if (t == 0) {
        int old = atomicAdd(&g_cnt[b], 1);
        s_last = (old == NPART - 1);
    }
    __syncthreads();
    if (!s_last) return;

    // ---- fused combine (last block of batch b) ----
    float M = g_pm[b * NPART + 0];
#pragma unroll
    for (int p = 1; p < NPART; p++) M = fmaxf(M, g_pm[b * NPART + p]);
    float L = 0.0f;
    float sc[NPART];
#pragma unroll
    for (int p = 0; p < NPART; p++) {
        sc[p] = __expf(g_pm[b * NPART + p] - M);
        L += sc[p] * g_pl[b * NPART + p];
    }
    const float invL = 1.0f / L;

    // context[b, :]: thread t owns float4 index t (256*4 = 1024)
    float4 csum = make_float4(0.f, 0.f, 0.f, 0.f);
#pragma unroll
    for (int p = 0; p < NPART; p++) {
        float4 v = reinterpret_cast<const float4*>(
            g_pctx + (size_t)(b * NPART + p) * HDIM)[t];
        csum.x += sc[p] * v.x; csum.y += sc[p] * v.y;
        csum.z += sc[p] * v.z; csum.w += sc[p] * v.w;
    }
    csum.x *= invL; csum.y *= invL; csum.z *= invL; csum.w *= invL;
    reinterpret_cast<float4*>(out + (size_t)b * HDIM)[t] = csum;

    // weight[b, :]
    float* __restrict__ wout = out + (size_t)BATCH * HDIM + (size_t)b * SLEN;
    const float* __restrict__ sc_in = g_scores + (size_t)b * SLEN;
#pragma unroll
    for (int i = 0; i < SLEN / 256; i++) {
        const int s = i * 256 + t;
        wout[s] = __expf(sc_in[s] - M) * invL;
    }

    // self-reset counter for next graph replay
    if (t == 0) g_cnt[b] = 0;
}

// ---------------------------------------------------------------------------
extern "C" void kernel_launch(void* const* d_in, const int* in_sizes, int n_in,
                              void* d_out, int out_size) {
    // inputs (metadata order): query, keys, W, U, V
    const float* keys = (const float*)d_in[1];
    const float* U    = (const float*)d_in[3];
    const float* V    = (const float*)d_in[4];
    float* out = (float*)d_out;

    vprime_kernel<<<dim3(8, VCHUNKS), 128>>>(U, V);
    vreduce_kernel<<<8, 128>>>();
    main_pass_kernel<<<dim3(NSB, BATCH), 256>>>(keys, out);
}

// round 5
// speedup vs baseline: 1.0386x; 1.0386x over previous
#include <cuda_runtime.h>
#include <cuda_bf16.h>
#include <cstddef>

#define HDIM 1024
#define SLEN 4096
#define BATCH 32
#define NSB 8                              // s-blocks per batch
#define ROWS_PER_BLOCK (SLEN / NSB)        // 512
#define NWARPS 8
#define ROWS_PER_WARP (ROWS_PER_BLOCK / NWARPS)  // 64
#define NPART NSB                          // 8 block-level partials per batch
#define VCHUNKS 64                         // o-chunks for vprime

// Scratch (device globals; no allocation in kernel_launch)
__device__ float g_vpart[VCHUNKS][HDIM];           // partial U^T V
__device__ float g_vprime[HDIM];                   // reduced U^T V
__device__ float g_scores[BATCH * SLEN];           // raw scores
__device__ float g_pctx[(size_t)BATCH * NPART * HDIM]; // block partials (1 MB)
__device__ float g_pm[BATCH * NPART];
__device__ float g_pl[BATCH * NPART];

// ---------------------------------------------------------------------------
// K1: v' partials. grid (8, 64), block 128. 512 CTAs, 16-deep unrolled loop.
// ---------------------------------------------------------------------------
__global__ void vprime_kernel(const float* __restrict__ U,
                              const float* __restrict__ V) {
    const int h  = blockIdx.x * 128 + threadIdx.x;
    const int oc = blockIdx.y;
    const int o0 = oc * (HDIM / VCHUNKS);
    float acc = 0.0f;
#pragma unroll
    for (int o = 0; o < HDIM / VCHUNKS; o++) {      // 16, fully unrolled
        acc += U[(size_t)(o0 + o) * HDIM + h] * V[o0 + o];
    }
    g_vpart[oc][h] = acc;
}

// K1b: reduce the 64 partials. grid 8, block 128.
__global__ void vreduce_kernel() {
    const int h = blockIdx.x * 128 + threadIdx.x;
    float a = 0.0f;
#pragma unroll
    for (int oc = 0; oc < VCHUNKS; oc++) a += g_vpart[oc][h];
    g_vprime[h] = a;
}

// ---------------------------------------------------------------------------
// K2: single streaming pass over keys (512 MB, read once, __ldcs).
// Each warp: 64 rows. Online softmax in registers; at block end the 8 warp
// partials are merged in smem -> ONE partial per block (8 per batch).
// grid (NSB, BATCH), block 256, occ 2.
// ---------------------------------------------------------------------------
__global__ void __launch_bounds__(256, 2)
main_pass_kernel(const float* __restrict__ keys) {
    const int b    = blockIdx.y;
    const int sb   = blockIdx.x;
    const int w    = threadIdx.x >> 5;
    const int lane = threadIdx.x & 31;
    const int t    = threadIdx.x;

    __shared__ float4 s_acc[NWARPS][256];   // 32 KB
    __shared__ float  s_m[NWARPS];
    __shared__ float  s_l[NWARPS];

    // v' into registers: lane covers float4 index i*32+lane
    float4 vp[8];
#pragma unroll
    for (int i = 0; i < 8; i++)
        vp[i] = reinterpret_cast<const float4*>(g_vprime)[i * 32 + lane];

    float m = -3.0e38f;
    float l = 0.0f;
    float4 acc[8];
#pragma unroll
    for (int i = 0; i < 8; i++) acc[i] = make_float4(0.f, 0.f, 0.f, 0.f);

    const int s0 = sb * ROWS_PER_BLOCK + w * ROWS_PER_WARP;
    const float4* __restrict__ base =
        reinterpret_cast<const float4*>(keys + (size_t)b * SLEN * HDIM);

    for (int j = 0; j < ROWS_PER_WARP; j++) {
        const int s = s0 + j;
        const float4* __restrict__ row = base + (size_t)s * (HDIM / 4);

        float4 k[8];
#pragma unroll
        for (int i = 0; i < 8; i++) k[i] = __ldcs(row + i * 32 + lane);

        float d = 0.0f;
#pragma unroll
        for (int i = 0; i < 8; i++) {
            d += k[i].x * vp[i].x + k[i].y * vp[i].y +
                 k[i].z * vp[i].z + k[i].w * vp[i].w;
        }
#pragma unroll
        for (int off = 16; off; off >>= 1)
            d += __shfl_xor_sync(0xffffffffu, d, off);

        if (lane == 0) g_scores[b * SLEN + s] = d;

        if (d > m) {  // warp-uniform; taken ~log2(64) times
            float sc = __expf(m - d);
            l *= sc;
#pragma unroll
            for (int i = 0; i < 8; i++) {
                acc[i].x *= sc; acc[i].y *= sc; acc[i].z *= sc; acc[i].w *= sc;
            }
            m = d;
        }
        float p = __expf(d - m);
        l += p;
#pragma unroll
        for (int i = 0; i < 8; i++) {
            acc[i].x += p * k[i].x; acc[i].y += p * k[i].y;
            acc[i].z += p * k[i].z; acc[i].w += p * k[i].w;
        }
    }

    // ---- block-level merge of 8 warp partials ----
#pragma unroll
    for (int i = 0; i < 8; i++) s_acc[w][i * 32 + lane] = acc[i];
    if (lane == 0) { s_m[w] = m; s_l[w] = l; }
    __syncthreads();

    float M = s_m[0];
#pragma unroll
    for (int ww = 1; ww < NWARPS; ww++) M = fmaxf(M, s_m[ww]);
    float L = 0.0f;
    float scale[NWARPS];
#pragma unroll
    for (int ww = 0; ww < NWARPS; ww++) {
        scale[ww] = __expf(s_m[ww] - M);
        L += scale[ww] * s_l[ww];
    }

    float4 sum = make_float4(0.f, 0.f, 0.f, 0.f);
#pragma unroll
    for (int ww = 0; ww < NWARPS; ww++) {
        float4 v = s_acc[ww][t];
        const float sc = scale[ww];
        sum.x += sc * v.x; sum.y += sc * v.y;
        sum.z += sc * v.z; sum.w += sc * v.w;
    }

    const int pidx = b * NPART + sb;
    reinterpret_cast<float4*>(g_pctx + (size_t)pidx * HDIM)[t] = sum;
    if (t == 0) { g_pm[pidx] = M; g_pl[pidx] = L; }
}

// ---------------------------------------------------------------------------
// K3: merge 8 partials per batch + emit outputs.
// grid (BATCH, 8), block 256. Block (b,chunk): 32 context float4s
// (h4 in [chunk*32,+32)) + 512 weights (s in [chunk*512,+512)).
// out layout: [context B*H | weight B*S]
// ---------------------------------------------------------------------------
__global__ void combine_kernel(float* __restrict__ out) {
    const int b     = blockIdx.x;
    const int chunk = blockIdx.y;     // 0..7
    const int t     = threadIdx.x;    // 0..255

    // every thread computes M/L over the 8 partials (independent loads, MLP 8)
    float pm[NPART];
#pragma unroll
    for (int p = 0; p < NPART; p++) pm[p] = g_pm[b * NPART + p];
    float M = pm[0];
#pragma unroll
    for (int p = 1; p < NPART; p++) M = fmaxf(M, pm[p]);
    float L = 0.0f;
    float sc[NPART];
#pragma unroll
    for (int p = 0; p < NPART; p++) {
        sc[p] = __expf(pm[p] - M);
        L += sc[p] * g_pl[b * NPART + p];
    }
    const float invL = 1.0f / L;

    // context: 32 float4 columns per block
    if (t < 32) {
        const int h4 = chunk * 32 + t;
        float4 sum = make_float4(0.f, 0.f, 0.f, 0.f);
#pragma unroll
        for (int p = 0; p < NPART; p++) {
            float4 v = reinterpret_cast<const float4*>(
                g_pctx + (size_t)(b * NPART + p) * HDIM)[h4];
            sum.x += sc[p] * v.x; sum.y += sc[p] * v.y;
            sum.z += sc[p] * v.z; sum.w += sc[p] * v.w;
        }
        sum.x *= invL; sum.y *= invL; sum.z *= invL; sum.w *= invL;
        reinterpret_cast<float4*>(out + (size_t)b * HDIM)[h4] = sum;
    }

    // weights: 512 per block
    float* __restrict__ wout = out + (size_t)BATCH * HDIM + (size_t)b * SLEN;
    const float* __restrict__ sc_in = g_scores + (size_t)b * SLEN;
#pragma unroll
    for (int i = 0; i < 2; i++) {
        const int s = chunk * 512 + i * 256 + t;
        wout[s] = __expf(sc_in[s] - M) * invL;
    }
}

// ---------------------------------------------------------------------------
extern "C" void kernel_launch(void* const* d_in, const int* in_sizes, int n_in,
                              void* d_out, int out_size) {
    // inputs (metadata order): query, keys, W, U, V
    const float* keys = (const float*)d_in[1];
    const float* U    = (const float*)d_in[3];
    const float* V    = (const float*)d_in[4];
    float* out = (float*)d_out;

    vprime_kernel<<<dim3(8, VCHUNKS), 128>>>(U, V);
    vreduce_kernel<<<8, 128>>>();
    main_pass_kernel<<<dim3(NSB, BATCH), 256>>>(keys);
    combine_kernel<<<dim3(BATCH, 8), 256>>>(out);
}

// round 6
// speedup vs baseline: 1.0653x; 1.0258x over previous
#include <cuda_runtime.h>
#include <cuda_bf16.h>
#include <cstddef>
#include <cstdint>

#define HDIM 1024
#define SLEN 4096
#define BATCH 32
#define NSB 8                              // s-blocks per batch = cluster size
#define ROWS_PER_BLOCK (SLEN / NSB)        // 512
#define NWARPS 8
#define ROWS_PER_WARP (ROWS_PER_BLOCK / NWARPS)  // 64
#define VCHUNKS 64                         // o-chunks for vprime

// Scratch (device globals; no allocation in kernel_launch)
__device__ float g_vpart[VCHUNKS][HDIM];           // partial U^T V
__device__ float g_vprime[HDIM];                   // reduced U^T V

// ---------------- DSMEM / cluster helpers ----------------
__device__ __forceinline__ uint32_t smem_u32(const void* p) {
    return (uint32_t)__cvta_generic_to_shared(p);
}
__device__ __forceinline__ uint32_t mapa_rank(uint32_t addr, uint32_t rank) {
    uint32_t r;
    asm("mapa.shared::cluster.u32 %0, %1, %2;" : "=r"(r) : "r"(addr), "r"(rank));
    return r;
}
__device__ __forceinline__ float2 ld_dsmem_f2(uint32_t a) {
    float2 v;
    asm volatile("ld.shared::cluster.v2.f32 {%0,%1}, [%2];"
                 : "=f"(v.x), "=f"(v.y) : "r"(a));
    return v;
}
__device__ __forceinline__ float4 ld_dsmem_f4(uint32_t a) {
    float4 v;
    asm volatile("ld.shared::cluster.v4.f32 {%0,%1,%2,%3}, [%4];"
                 : "=f"(v.x), "=f"(v.y), "=f"(v.z), "=f"(v.w) : "r"(a));
    return v;
}
#define CLUSTER_SYNC() do { \
    asm volatile("barrier.cluster.arrive.aligned;" ::: "memory"); \
    asm volatile("barrier.cluster.wait.aligned;" ::: "memory"); \
} while (0)

// ---------------------------------------------------------------------------
// K1: v' partials. grid (8, 64), block 128.
// ---------------------------------------------------------------------------
__global__ void vprime_kernel(const float* __restrict__ U,
                              const float* __restrict__ V) {
    const int h  = blockIdx.x * 128 + threadIdx.x;
    const int oc = blockIdx.y;
    const int o0 = oc * (HDIM / VCHUNKS);
    float acc = 0.0f;
#pragma unroll
    for (int o = 0; o < HDIM / VCHUNKS; o++) {      // 16, fully unrolled
        acc += U[(size_t)(o0 + o) * HDIM + h] * V[o0 + o];
    }
    g_vpart[oc][h] = acc;
}

// K1b: reduce the 64 partials. grid 8, block 128.
__global__ void vreduce_kernel() {
    const int h = blockIdx.x * 128 + threadIdx.x;
    float a = 0.0f;
#pragma unroll
    for (int oc = 0; oc < VCHUNKS; oc++) a += g_vpart[oc][h];
    g_vprime[h] = a;
}

// ---------------------------------------------------------------------------
// K2: single streaming pass over keys (512 MB, read once, __ldcs), fully
// fused: the 8 CTAs of a batch form a cluster; block partials + raw scores
// stay in SMEM; after cluster.sync each CTA merges peers' partials via DSMEM
// and writes its 1/8 of context + weights. No combine kernel, no global
// partials, no fences/atomics.
// grid (NSB, BATCH), cluster (NSB,1,1), block 256, occ 2.
// out layout: [context B*H | weight B*S]
// ---------------------------------------------------------------------------
__global__ void __launch_bounds__(256, 2) __cluster_dims__(NSB, 1, 1)
main_pass_kernel(const float* __restrict__ keys, float* __restrict__ out) {
    const int b    = blockIdx.y;
    const int sb   = blockIdx.x;          // == cluster rank
    const int w    = threadIdx.x >> 5;
    const int lane = threadIdx.x & 31;
    const int t    = threadIdx.x;

    __shared__ float4 s_acc[NWARPS][256];      // 32 KB warp partials
    __shared__ float  s_m[NWARPS];
    __shared__ float  s_l[NWARPS];
    __shared__ float4 s_bacc[256];             // 4 KB block partial acc
    __shared__ float2 s_ml;                    // block partial (M, L)
    __shared__ float  s_scores[ROWS_PER_BLOCK];// 2 KB raw scores
    __shared__ float  s_pm[NSB], s_pl[NSB];    // gathered peer M/L

    // v' into registers: lane covers float4 index i*32+lane
    float4 vp[8];
#pragma unroll
    for (int i = 0; i < 8; i++)
        vp[i] = reinterpret_cast<const float4*>(g_vprime)[i * 32 + lane];

    float m = -3.0e38f;
    float l = 0.0f;
    float4 acc[8];
#pragma unroll
    for (int i = 0; i < 8; i++) acc[i] = make_float4(0.f, 0.f, 0.f, 0.f);

    const int s0 = sb * ROWS_PER_BLOCK + w * ROWS_PER_WARP;
    const float4* __restrict__ base =
        reinterpret_cast<const float4*>(keys + (size_t)b * SLEN * HDIM);

    for (int j = 0; j < ROWS_PER_WARP; j++) {
        const int s = s0 + j;
        const float4* __restrict__ row = base + (size_t)s * (HDIM / 4);

        float4 k[8];
#pragma unroll
        for (int i = 0; i < 8; i++) k[i] = __ldcs(row + i * 32 + lane);

        float d = 0.0f;
#pragma unroll
        for (int i = 0; i < 8; i++) {
            d += k[i].x * vp[i].x + k[i].y * vp[i].y +
                 k[i].z * vp[i].z + k[i].w * vp[i].w;
        }
#pragma unroll
        for (int off = 16; off; off >>= 1)
            d += __shfl_xor_sync(0xffffffffu, d, off);

        if (lane == 0) s_scores[w * ROWS_PER_WARP + j] = d;

        if (d > m) {  // warp-uniform; taken ~log2(64) times
            float sc = __expf(m - d);
            l *= sc;
#pragma unroll
            for (int i = 0; i < 8; i++) {
                acc[i].x *= sc; acc[i].y *= sc; acc[i].z *= sc; acc[i].w *= sc;
            }
            m = d;
        }
        float p = __expf(d - m);
        l += p;
#pragma unroll
        for (int i = 0; i < 8; i++) {
            acc[i].x += p * k[i].x; acc[i].y += p * k[i].y;
            acc[i].z += p * k[i].z; acc[i].w += p * k[i].w;
        }
    }

    // ---- block-level merge of 8 warp partials (smem) ----
#pragma unroll
    for (int i = 0; i < 8; i++) s_acc[w][i * 32 + lane] = acc[i];
    if (lane == 0) { s_m[w] = m; s_l[w] = l; }
    __syncthreads();

    float Mb = s_m[0];
#pragma unroll
    for (int ww = 1; ww < NWARPS; ww++) Mb = fmaxf(Mb, s_m[ww]);
    float Lb = 0.0f;
    float scale[NWARPS];
#pragma unroll
    for (int ww = 0; ww < NWARPS; ww++) {
        scale[ww] = __expf(s_m[ww] - Mb);
        Lb += scale[ww] * s_l[ww];
    }

    float4 bsum = make_float4(0.f, 0.f, 0.f, 0.f);
#pragma unroll
    for (int ww = 0; ww < NWARPS; ww++) {
        float4 v = s_acc[ww][t];
        const float sc = scale[ww];
        bsum.x += sc * v.x; bsum.y += sc * v.y;
        bsum.z += sc * v.z; bsum.w += sc * v.w;
    }
    s_bacc[t] = bsum;
    if (t == 0) { s_ml.x = Mb; s_ml.y = Lb; }
    __syncthreads();

    // ---- cluster-wide merge via DSMEM ----
    CLUSTER_SYNC();

    if (t < NSB) {
        uint32_t a = mapa_rank(smem_u32(&s_ml), (uint32_t)t);
        float2 ml = ld_dsmem_f2(a);
        s_pm[t] = ml.x; s_pl[t] = ml.y;
    }
    __syncthreads();

    float M = s_pm[0];
#pragma unroll
    for (int p = 1; p < NSB; p++) M = fmaxf(M, s_pm[p]);
    float L = 0.0f;
    float scg[NSB];
#pragma unroll
    for (int p = 0; p < NSB; p++) {
        scg[p] = __expf(s_pm[p] - M);
        L += scg[p] * s_pl[p];
    }
    const float invL = 1.0f / L;

    // context slice: this CTA owns float4 columns [sb*32, sb*32+32)
    if (t < 32) {
        const int h4 = sb * 32 + t;
        const uint32_t loc = smem_u32(&s_bacc[h4]);
        float4 cs = make_float4(0.f, 0.f, 0.f, 0.f);
#pragma unroll
        for (int p = 0; p < NSB; p++) {
            float4 v = ld_dsmem_f4(mapa_rank(loc, (uint32_t)p));
            cs.x += scg[p] * v.x; cs.y += scg[p] * v.y;
            cs.z += scg[p] * v.z; cs.w += scg[p] * v.w;
        }
        cs.x *= invL; cs.y *= invL; cs.z *= invL; cs.w *= invL;
        reinterpret_cast<float4*>(out + (size_t)b * HDIM)[h4] = cs;
    }

    // weights for this CTA's 512 rows
    float* __restrict__ wout =
        out + (size_t)BATCH * HDIM + (size_t)b * SLEN + (size_t)sb * ROWS_PER_BLOCK;
#pragma unroll
    for (int i = 0; i < ROWS_PER_BLOCK / 256; i++) {
        const int s = i * 256 + t;
        wout[s] = __expf(s_scores[s] - M) * invL;
    }

    // protect SMEM until all peers finished their DSMEM reads
    CLUSTER_SYNC();
}

// ---------------------------------------------------------------------------
extern "C" void kernel_launch(void* const* d_in, const int* in_sizes, int n_in,
                              void* d_out, int out_size) {
    // inputs (metadata order): query, keys, W, U, V
    const float* keys = (const float*)d_in[1];
    const float* U    = (const float*)d_in[3];
    const float* V    = (const float*)d_in[4];
    float* out = (float*)d_out;

    vprime_kernel<<<dim3(8, VCHUNKS), 128>>>(U, V);
    vreduce_kernel<<<8, 128>>>();
    main_pass_kernel<<<dim3(NSB, BATCH), 256>>>(keys, out);
}